// round 1
// baseline (speedup 1.0000x reference)
#include <cuda_runtime.h>
#include <cstdint>

// Problem constants
constexpr int Bc = 8, Lc = 4096, Pc = 256, Hc = 256;
constexpr int Mrows = Bc * Lc;          // 32768
constexpr int NCHUNK = 64, CLEN = 64;   // 64 chunks of 64 steps

// Scratch (static device arrays -- no allocation allowed)
__device__ float g_f [(size_t)Mrows * 512];   // f  = dt_s*Bu : [bl][re(p) | im(p)]
__device__ float g_ys[(size_t)Mrows * 512];   // ys layout identical
__device__ float g_Bop[256 * 512];            // [h][n], n = p (re) | 256+p (im), dt_s folded
__device__ float g_Cop[512 * 256];            // [kk][h], kk<256: +Cre ; kk>=256: -Cim
__device__ float g_m11[256], g_m12[256], g_dts[256];
__device__ float g_cf  [Bc * NCHUNK * 4 * 256]; // chunk-final states (x1r,x1i,x2r,x2i planes)
__device__ float g_init[Bc * NCHUNK * 4 * 256]; // corrected chunk-initial states

__device__ __forceinline__ float tf32_rna(float x) {
    uint32_t u;
    asm("cvt.rna.tf32.f32 %0, %1;" : "=r"(u) : "f"(x));
    return __uint_as_float(u);
}

__device__ __forceinline__ void cp_async16(void* smem, const void* gmem) {
    uint32_t s = (uint32_t)__cvta_generic_to_shared(smem);
    asm volatile("cp.async.ca.shared.global [%0], [%1], 16;\n" :: "r"(s), "l"(gmem));
}

__device__ __forceinline__ void mma_tf32(float c[4], const uint32_t a[4], const uint32_t b[2]) {
    asm volatile(
        "mma.sync.aligned.m16n8k8.row.col.f32.tf32.tf32.f32 "
        "{%0,%1,%2,%3}, {%4,%5,%6,%7}, {%8,%9}, {%0,%1,%2,%3};\n"
        : "+f"(c[0]), "+f"(c[1]), "+f"(c[2]), "+f"(c[3])
        : "r"(a[0]), "r"(a[1]), "r"(a[2]), "r"(a[3]), "r"(b[0]), "r"(b[1]));
}

// ---------------------------------------------------------------------------
// Prep: per-p recurrence params + operand matrices (tf32-rounded, scaled)
// ---------------------------------------------------------------------------
__global__ void prep_kernel(const float* __restrict__ Ad, const float* __restrict__ Gd,
                            const float* __restrict__ dt, const float* __restrict__ Bm,
                            const float* __restrict__ Cm) {
    int h = blockIdx.x;          // 0..255
    int n = threadIdx.x;         // 0..511
    int p = n & 255;
    int c = n >> 8;              // 0=re, 1=im
    float dts = 1.0f / (1.0f + expf(-dt[p]));
    float G = fmaxf(Gd[p], dts * Ad[p]);
    float A = fmaxf(Ad[p], 0.25f * G * G);

    // Bop[h][n] = dt_s[p] * B[p][h][c]
    g_Bop[h * 512 + n] = tf32_rna(dts * Bm[p * 512 + h * 2 + c]);
    // Cop[kk=n][h] = +Cre[h][p] (c==0) | -Cim[h][p] (c==1)
    float cv = Cm[h * 512 + p * 2 + c];
    g_Cop[n * 256 + h] = tf32_rna(c ? -cv : cv);

    if (h == 0 && c == 0) {
        g_m11[p] = 1.0f - dts * G;
        g_m12[p] = -dts * A;
        g_dts[p] = dts;          // m21; m22 == 1
    }
}

// ---------------------------------------------------------------------------
// tf32 GEMM: C[M x N] = A[M x K] @ B[K x N] (+ optional D*u epilogue)
// 128x128x32 block tile, 8 warps (2x4), warp tile 64x32, m16n8k8 mma
// ---------------------------------------------------------------------------
template <int N, int K, bool EPI>
__global__ void __launch_bounds__(256, 2)
gemm_tf32(const float* __restrict__ A, const float* __restrict__ Bm,
          float* __restrict__ C, const float* __restrict__ U,
          const float* __restrict__ Dv) {
    extern __shared__ float sm[];
    float* As = sm;               // 2 stages * 128*36
    float* Bs = sm + 2 * 128 * 36; // 2 stages * 32*136

    const int tid  = threadIdx.x;
    const int lane = tid & 31, warp = tid >> 5;
    const int g = lane >> 2, t = lane & 3;
    const int wr = (warp & 1) * 64, wc = (warp >> 1) * 32;
    const int m0 = blockIdx.y * 128, n0 = blockIdx.x * 128;
    const int nk = K / 32;

    float acc[4][4][4];
#pragma unroll
    for (int i = 0; i < 4; i++)
#pragma unroll
        for (int j = 0; j < 4; j++)
#pragma unroll
            for (int q = 0; q < 4; q++) acc[i][j][q] = 0.0f;

    float4 aReg[4];

    auto ldgA = [&](int kt) {
#pragma unroll
        for (int i = 0; i < 4; i++) {
            int idx = i * 256 + tid;
            int m = idx >> 3, c4 = idx & 7;
            aReg[i] = *reinterpret_cast<const float4*>(
                A + (size_t)(m0 + m) * K + kt * 32 + c4 * 4);
        }
    };
    auto stsA = [&](int s) {
#pragma unroll
        for (int i = 0; i < 4; i++) {
            int idx = i * 256 + tid;
            int m = idx >> 3, c4 = idx & 7;
            float4 v = aReg[i];
            v.x = tf32_rna(v.x); v.y = tf32_rna(v.y);
            v.z = tf32_rna(v.z); v.w = tf32_rna(v.w);
            *reinterpret_cast<float4*>(As + s * 4608 + m * 36 + c4 * 4) = v;
        }
    };
    auto ldB = [&](int s, int kt) {
#pragma unroll
        for (int i = 0; i < 4; i++) {
            int idx = i * 256 + tid;
            int k = idx >> 5, c = idx & 31;
            cp_async16(Bs + s * 4352 + k * 136 + c * 4,
                       Bm + (size_t)(kt * 32 + k) * N + n0 + c * 4);
        }
        asm volatile("cp.async.commit_group;\n" ::);
    };

    // prologue
    ldB(0, 0);
    ldgA(0); stsA(0);
    asm volatile("cp.async.wait_group 0;\n" ::);
    __syncthreads();

    for (int kt = 0; kt < nk; kt++) {
        int s = kt & 1;
        bool more = (kt + 1 < nk);
        if (more) { ldB(s ^ 1, kt + 1); ldgA(kt + 1); }

        const float* Asb = As + s * 4608;
        const float* Bsb = Bs + s * 4352;
#pragma unroll
        for (int kk = 0; kk < 4; kk++) {
            uint32_t af[4][4];
#pragma unroll
            for (int mt = 0; mt < 4; mt++) {
                int row = wr + mt * 16 + g;
                int col = kk * 8 + t;
                af[mt][0] = __float_as_uint(Asb[row * 36 + col]);
                af[mt][1] = __float_as_uint(Asb[(row + 8) * 36 + col]);
                af[mt][2] = __float_as_uint(Asb[row * 36 + col + 4]);
                af[mt][3] = __float_as_uint(Asb[(row + 8) * 36 + col + 4]);
            }
            uint32_t bf[4][2];
#pragma unroll
            for (int nt = 0; nt < 4; nt++) {
                int col = wc + nt * 8 + g;
                bf[nt][0] = __float_as_uint(Bsb[(kk * 8 + t) * 136 + col]);
                bf[nt][1] = __float_as_uint(Bsb[(kk * 8 + t + 4) * 136 + col]);
            }
#pragma unroll
            for (int mt = 0; mt < 4; mt++)
#pragma unroll
                for (int nt = 0; nt < 4; nt++)
                    mma_tf32(acc[mt][nt], af[mt], bf[nt]);
        }
        if (more) {
            stsA(s ^ 1);
            asm volatile("cp.async.wait_group 0;\n" ::);
        }
        __syncthreads();
    }

    // epilogue
#pragma unroll
    for (int mt = 0; mt < 4; mt++) {
#pragma unroll
        for (int nt = 0; nt < 4; nt++) {
            int r0 = m0 + wr + mt * 16 + g;
            int cc = n0 + wc + nt * 8 + 2 * t;
            float v0 = acc[mt][nt][0], v1 = acc[mt][nt][1];
            float v2 = acc[mt][nt][2], v3 = acc[mt][nt][3];
            if (EPI) {
                float d0 = Dv[cc], d1 = Dv[cc + 1];
                v0 += d0 * U[(size_t)r0 * 256 + cc];
                v1 += d1 * U[(size_t)r0 * 256 + cc + 1];
                v2 += d0 * U[(size_t)(r0 + 8) * 256 + cc];
                v3 += d1 * U[(size_t)(r0 + 8) * 256 + cc + 1];
            }
            *reinterpret_cast<float2*>(C + (size_t)r0 * N + cc) = make_float2(v0, v1);
            *reinterpret_cast<float2*>(C + (size_t)(r0 + 8) * N + cc) = make_float2(v2, v3);
        }
    }
}

// ---------------------------------------------------------------------------
// Scan phase 1: per-chunk local scan (zero init) -> chunk-final states
// ---------------------------------------------------------------------------
__global__ void scan_local() {
    int b = blockIdx.x >> 6;
    int ch = blockIdx.x & 63;
    int p = threadIdx.x;
    float m11 = g_m11[p], m12 = g_m12[p], m21 = g_dts[p];
    float x1r = 0, x1i = 0, x2r = 0, x2i = 0;
    size_t base = ((size_t)(b * Lc + ch * CLEN)) * 512 + p;
#pragma unroll 4
    for (int j = 0; j < CLEN; j++) {
        float fr = g_f[base], fi = g_f[base + 256];
        float n1r = fmaf(m11, x1r, fmaf(m12, x2r, fr));
        float n2r = fmaf(m21, x1r, x2r);
        float n1i = fmaf(m11, x1i, fmaf(m12, x2i, fi));
        float n2i = fmaf(m21, x1i, x2i);
        x1r = n1r; x2r = n2r; x1i = n1i; x2i = n2i;
        base += 512;
    }
    int cb = (b * NCHUNK + ch) * 1024 + p;
    g_cf[cb] = x1r; g_cf[cb + 256] = x1i; g_cf[cb + 512] = x2r; g_cf[cb + 768] = x2i;
}

// ---------------------------------------------------------------------------
// Scan phase 2: sequential cross-chunk combine per (b,p) via M^CLEN
// ---------------------------------------------------------------------------
__global__ void scan_combine() {
    int b = blockIdx.x;
    int p = threadIdx.x;
    float m11 = g_m11[p], m12 = g_m12[p], m21 = g_dts[p];
    // M^CLEN
    float pa = 1, pb = 0, pc = 0, pd = 1;
#pragma unroll 4
    for (int i = 0; i < CLEN; i++) {
        float na = fmaf(m11, pa, m12 * pc);
        float nb = fmaf(m11, pb, m12 * pd);
        float nc = fmaf(m21, pa, pc);
        float nd = fmaf(m21, pb, pd);
        pa = na; pb = nb; pc = nc; pd = nd;
    }
    float x1r = 0, x1i = 0, x2r = 0, x2i = 0;
    for (int ch = 0; ch < NCHUNK; ch++) {
        int cb = (b * NCHUNK + ch) * 1024 + p;
        g_init[cb] = x1r; g_init[cb + 256] = x1i;
        g_init[cb + 512] = x2r; g_init[cb + 768] = x2i;
        float f1r = g_cf[cb],       f1i = g_cf[cb + 256];
        float f2r = g_cf[cb + 512], f2i = g_cf[cb + 768];
        float n1r = fmaf(pa, x1r, fmaf(pb, x2r, f1r));
        float n2r = fmaf(pc, x1r, fmaf(pd, x2r, f2r));
        float n1i = fmaf(pa, x1i, fmaf(pb, x2i, f1i));
        float n2i = fmaf(pc, x1i, fmaf(pd, x2i, f2i));
        x1r = n1r; x2r = n2r; x1i = n1i; x2i = n2i;
    }
}

// ---------------------------------------------------------------------------
// Scan phase 3: re-scan each chunk from corrected init, write ys (x2)
// ---------------------------------------------------------------------------
__global__ void scan_final() {
    int b = blockIdx.x >> 6;
    int ch = blockIdx.x & 63;
    int p = threadIdx.x;
    float m11 = g_m11[p], m12 = g_m12[p], m21 = g_dts[p];
    int cb = (b * NCHUNK + ch) * 1024 + p;
    float x1r = g_init[cb],       x1i = g_init[cb + 256];
    float x2r = g_init[cb + 512], x2i = g_init[cb + 768];
    size_t base = ((size_t)(b * Lc + ch * CLEN)) * 512 + p;
#pragma unroll 4
    for (int j = 0; j < CLEN; j++) {
        float fr = g_f[base], fi = g_f[base + 256];
        float n1r = fmaf(m11, x1r, fmaf(m12, x2r, fr));
        float n2r = fmaf(m21, x1r, x2r);
        float n1i = fmaf(m11, x1i, fmaf(m12, x2i, fi));
        float n2i = fmaf(m21, x1i, x2i);
        x1r = n1r; x2r = n2r; x1i = n1i; x2i = n2i;
        g_ys[base] = x2r;
        g_ys[base + 256] = x2i;
        base += 512;
    }
}

// ---------------------------------------------------------------------------
extern "C" void kernel_launch(void* const* d_in, const int* in_sizes, int n_in,
                              void* d_out, int out_size) {
    const float* u  = (const float*)d_in[0];
    const float* Ad = (const float*)d_in[1];
    const float* Gd = (const float*)d_in[2];
    const float* dt = (const float*)d_in[3];
    const float* Bm = (const float*)d_in[4];
    const float* Cm = (const float*)d_in[5];
    const float* Dv = (const float*)d_in[6];
    float* out = (float*)d_out;

    float *fptr, *ysptr, *bop, *cop;
    cudaGetSymbolAddress((void**)&fptr,  g_f);
    cudaGetSymbolAddress((void**)&ysptr, g_ys);
    cudaGetSymbolAddress((void**)&bop,   g_Bop);
    cudaGetSymbolAddress((void**)&cop,   g_Cop);

    const int smem_bytes = (2 * 128 * 36 + 2 * 32 * 136) * 4; // 71680
    cudaFuncSetAttribute(gemm_tf32<512, 256, false>,
                         cudaFuncAttributeMaxDynamicSharedMemorySize, smem_bytes);
    cudaFuncSetAttribute(gemm_tf32<256, 512, true>,
                         cudaFuncAttributeMaxDynamicSharedMemorySize, smem_bytes);

    prep_kernel<<<256, 512>>>(Ad, Gd, dt, Bm, Cm);

    // GEMM1: f[bl][n(512)] = u[bl][h] @ Bop[h][n]
    gemm_tf32<512, 256, false><<<dim3(4, 256), 256, smem_bytes>>>(u, bop, fptr, nullptr, nullptr);

    scan_local  <<<Bc * NCHUNK, 256>>>();
    scan_combine<<<Bc, 256>>>();
    scan_final  <<<Bc * NCHUNK, 256>>>();

    // GEMM2: out[bl][h] = ys[bl][kk(512)] @ Cop[kk][h] + D[h]*u[bl][h]
    gemm_tf32<256, 512, true><<<dim3(2, 256), 256, smem_bytes>>>(ysptr, cop, out, u, Dv);
}

// round 2
// speedup vs baseline: 1.1250x; 1.1250x over previous
#include <cuda_runtime.h>
#include <cstdint>

// Problem constants
constexpr int Bc = 8, Lc = 4096, Pc = 256, Hc = 256;
constexpr int Mrows = Bc * Lc;          // 32768
constexpr int NCHUNK = 64, CLEN = 64;   // 64 chunks of 64 steps

// Scratch (static device arrays -- no allocation allowed)
__device__ float g_f [(size_t)Mrows * 512];   // f = dt_s*Bu : [bl][2p+c] (re/im interleaved)
__device__ float g_ys[(size_t)Mrows * 512];   // ys, same interleaved layout
__device__ float g_Bop[256 * 512];            // [h][n], n = 2p+c, dt_s folded
__device__ float g_Cop[512 * 256];            // [kk][h], kk = 2p+c: +Cre / -Cim
__device__ float g_m11[256], g_m12[256], g_dts[256];
__device__ float g_cf  [Bc * 256 * NCHUNK * 4]; // [b][p][ch] float4 (x1r,x1i,x2r,x2i)
__device__ float g_init[Bc * 256 * NCHUNK * 4]; // same layout

__device__ __forceinline__ float tf32_rna(float x) {
    uint32_t u;
    asm("cvt.rna.tf32.f32 %0, %1;" : "=r"(u) : "f"(x));
    return __uint_as_float(u);
}

__device__ __forceinline__ void cp_async16(void* smem, const void* gmem) {
    uint32_t s = (uint32_t)__cvta_generic_to_shared(smem);
    asm volatile("cp.async.ca.shared.global [%0], [%1], 16;\n" :: "r"(s), "l"(gmem));
}

__device__ __forceinline__ void mma_tf32(float c[4], const uint32_t a[4], const uint32_t b[2]) {
    asm volatile(
        "mma.sync.aligned.m16n8k8.row.col.f32.tf32.tf32.f32 "
        "{%0,%1,%2,%3}, {%4,%5,%6,%7}, {%8,%9}, {%0,%1,%2,%3};\n"
        : "+f"(c[0]), "+f"(c[1]), "+f"(c[2]), "+f"(c[3])
        : "r"(a[0]), "r"(a[1]), "r"(a[2]), "r"(a[3]), "r"(b[0]), "r"(b[1]));
}

// ---------------------------------------------------------------------------
// Prep: per-p recurrence params + operand matrices (tf32-rounded, scaled)
// Layout: interleaved n = 2p + c  (c=0 re, c=1 im)
// ---------------------------------------------------------------------------
__global__ void prep_kernel(const float* __restrict__ Ad, const float* __restrict__ Gd,
                            const float* __restrict__ dt, const float* __restrict__ Bm,
                            const float* __restrict__ Cm) {
    int h = blockIdx.x;          // 0..255
    int n = threadIdx.x;         // 0..511
    int p = n >> 1;
    int c = n & 1;
    float dts = 1.0f / (1.0f + expf(-dt[p]));
    float G = fmaxf(Gd[p], dts * Ad[p]);
    float A = fmaxf(Ad[p], 0.25f * G * G);

    // Bop[h][2p+c] = dt_s[p] * B[p][h][c]
    g_Bop[h * 512 + n] = tf32_rna(dts * Bm[p * 512 + h * 2 + c]);
    // Cop[2p+c][h] = +Cre[h][p] (c==0) | -Cim[h][p] (c==1)
    float cv = Cm[h * 512 + p * 2 + c];
    g_Cop[n * 256 + h] = tf32_rna(c ? -cv : cv);

    if (h == 0 && c == 0) {
        g_m11[p] = 1.0f - dts * G;
        g_m12[p] = -dts * A;
        g_dts[p] = dts;          // m21; m22 == 1
    }
}

// ---------------------------------------------------------------------------
// tf32 GEMM: C[M x N] = A[M x K] @ B[K x N] (+ optional D*u epilogue)
// ---------------------------------------------------------------------------
template <int N, int K, bool EPI>
__global__ void __launch_bounds__(256, 2)
gemm_tf32(const float* __restrict__ A, const float* __restrict__ Bm,
          float* __restrict__ C, const float* __restrict__ U,
          const float* __restrict__ Dv) {
    extern __shared__ float sm[];
    float* As = sm;                // 2 stages * 128*36
    float* Bs = sm + 2 * 128 * 36; // 2 stages * 32*136

    const int tid  = threadIdx.x;
    const int lane = tid & 31, warp = tid >> 5;
    const int g = lane >> 2, t = lane & 3;
    const int wr = (warp & 1) * 64, wc = (warp >> 1) * 32;
    const int m0 = blockIdx.y * 128, n0 = blockIdx.x * 128;
    const int nk = K / 32;

    float acc[4][4][4];
#pragma unroll
    for (int i = 0; i < 4; i++)
#pragma unroll
        for (int j = 0; j < 4; j++)
#pragma unroll
            for (int q = 0; q < 4; q++) acc[i][j][q] = 0.0f;

    float4 aReg[4];

    auto ldgA = [&](int kt) {
#pragma unroll
        for (int i = 0; i < 4; i++) {
            int idx = i * 256 + tid;
            int m = idx >> 3, c4 = idx & 7;
            aReg[i] = *reinterpret_cast<const float4*>(
                A + (size_t)(m0 + m) * K + kt * 32 + c4 * 4);
        }
    };
    auto stsA = [&](int s) {
#pragma unroll
        for (int i = 0; i < 4; i++) {
            int idx = i * 256 + tid;
            int m = idx >> 3, c4 = idx & 7;
            float4 v = aReg[i];
            v.x = tf32_rna(v.x); v.y = tf32_rna(v.y);
            v.z = tf32_rna(v.z); v.w = tf32_rna(v.w);
            *reinterpret_cast<float4*>(As + s * 4608 + m * 36 + c4 * 4) = v;
        }
    };
    auto ldB = [&](int s, int kt) {
#pragma unroll
        for (int i = 0; i < 4; i++) {
            int idx = i * 256 + tid;
            int k = idx >> 5, c = idx & 31;
            cp_async16(Bs + s * 4352 + k * 136 + c * 4,
                       Bm + (size_t)(kt * 32 + k) * N + n0 + c * 4);
        }
        asm volatile("cp.async.commit_group;\n" ::);
    };

    // prologue
    ldB(0, 0);
    ldgA(0); stsA(0);
    asm volatile("cp.async.wait_group 0;\n" ::);
    __syncthreads();

    for (int kt = 0; kt < nk; kt++) {
        int s = kt & 1;
        bool more = (kt + 1 < nk);
        if (more) { ldB(s ^ 1, kt + 1); ldgA(kt + 1); }

        const float* Asb = As + s * 4608;
        const float* Bsb = Bs + s * 4352;
#pragma unroll
        for (int kk = 0; kk < 4; kk++) {
            uint32_t af[4][4];
#pragma unroll
            for (int mt = 0; mt < 4; mt++) {
                int row = wr + mt * 16 + g;
                int col = kk * 8 + t;
                af[mt][0] = __float_as_uint(Asb[row * 36 + col]);
                af[mt][1] = __float_as_uint(Asb[(row + 8) * 36 + col]);
                af[mt][2] = __float_as_uint(Asb[row * 36 + col + 4]);
                af[mt][3] = __float_as_uint(Asb[(row + 8) * 36 + col + 4]);
            }
            uint32_t bf[4][2];
#pragma unroll
            for (int nt = 0; nt < 4; nt++) {
                int col = wc + nt * 8 + g;
                bf[nt][0] = __float_as_uint(Bsb[(kk * 8 + t) * 136 + col]);
                bf[nt][1] = __float_as_uint(Bsb[(kk * 8 + t + 4) * 136 + col]);
            }
#pragma unroll
            for (int mt = 0; mt < 4; mt++)
#pragma unroll
                for (int nt = 0; nt < 4; nt++)
                    mma_tf32(acc[mt][nt], af[mt], bf[nt]);
        }
        if (more) {
            stsA(s ^ 1);
            asm volatile("cp.async.wait_group 0;\n" ::);
        }
        __syncthreads();
    }

    // epilogue
#pragma unroll
    for (int mt = 0; mt < 4; mt++) {
#pragma unroll
        for (int nt = 0; nt < 4; nt++) {
            int r0 = m0 + wr + mt * 16 + g;
            int cc = n0 + wc + nt * 8 + 2 * t;
            float v0 = acc[mt][nt][0], v1 = acc[mt][nt][1];
            float v2 = acc[mt][nt][2], v3 = acc[mt][nt][3];
            if (EPI) {
                float d0 = Dv[cc], d1 = Dv[cc + 1];
                v0 += d0 * U[(size_t)r0 * 256 + cc];
                v1 += d1 * U[(size_t)r0 * 256 + cc + 1];
                v2 += d0 * U[(size_t)(r0 + 8) * 256 + cc];
                v3 += d1 * U[(size_t)(r0 + 8) * 256 + cc + 1];
            }
            *reinterpret_cast<float2*>(C + (size_t)r0 * N + cc) = make_float2(v0, v1);
            *reinterpret_cast<float2*>(C + (size_t)(r0 + 8) * N + cc) = make_float2(v2, v3);
        }
    }
}

// ---------------------------------------------------------------------------
// Scan phase 1: per-chunk local scan (zero init) -> chunk-final states
// ---------------------------------------------------------------------------
__global__ void scan_local() {
    int b = blockIdx.x >> 6;
    int ch = blockIdx.x & 63;
    int p = threadIdx.x;
    float m11 = g_m11[p], m12 = g_m12[p], m21 = g_dts[p];
    float x1r = 0, x1i = 0, x2r = 0, x2i = 0;
    const float2* f = reinterpret_cast<const float2*>(g_f)
                      + ((size_t)(b * Lc + ch * CLEN)) * 256 + p;
#pragma unroll 8
    for (int j = 0; j < CLEN; j++) {
        float2 fv = f[(size_t)j * 256];
        float n1r = fmaf(m11, x1r, fmaf(m12, x2r, fv.x));
        float n2r = fmaf(m21, x1r, x2r);
        float n1i = fmaf(m11, x1i, fmaf(m12, x2i, fv.y));
        float n2i = fmaf(m21, x1i, x2i);
        x1r = n1r; x2r = n2r; x1i = n1i; x2i = n2i;
    }
    reinterpret_cast<float4*>(g_cf)[(b * 256 + p) * 64 + ch] =
        make_float4(x1r, x1i, x2r, x2i);
}

// ---------------------------------------------------------------------------
// Scan phase 2: warp-parallel cross-chunk combine.
// One warp per (b,p). Element: x_{ch+1} = P x_ch + v_ch, P = M^64 (6 squarings).
// Lane j pre-combines chunks {2j, 2j+1}, then Kogge-Stone over 32 lanes.
// ---------------------------------------------------------------------------
__global__ void __launch_bounds__(256) scan_combine() {
    const unsigned FULL = 0xFFFFFFFFu;
    int wg = blockIdx.x * 8 + (threadIdx.x >> 5);   // 0..2047
    int lane = threadIdx.x & 31;
    int b = wg >> 8, p = wg & 255;

    float m11 = g_m11[p], m12 = g_m12[p], m21 = g_dts[p];
    // P = M^64 via 6 squarings; M = [m11 m12; m21 1]
    float pa = m11, pb = m12, pc = m21, pd = 1.0f;
#pragma unroll
    for (int i = 0; i < 6; i++) {
        float na = fmaf(pa, pa, pb * pc);
        float nb = fmaf(pa, pb, pb * pd);
        float nc = fmaf(pc, pa, pd * pc);
        float nd = fmaf(pc, pb, pd * pd);
        pa = na; pb = nb; pc = nc; pd = nd;
    }

    const float4* cf = reinterpret_cast<const float4*>(g_cf) + (size_t)(b * 256 + p) * 64;
    float4 v0 = cf[2 * lane];
    float4 v1 = cf[2 * lane + 1];

    // pair-combined affine part: w = P*v0 + v1 (complex 2-vec, real P)
    float w1r = fmaf(pa, v0.x, fmaf(pb, v0.z, v1.x));
    float w1i = fmaf(pa, v0.y, fmaf(pb, v0.w, v1.y));
    float w2r = fmaf(pc, v0.x, fmaf(pd, v0.z, v1.z));
    float w2i = fmaf(pc, v0.y, fmaf(pd, v0.w, v1.w));
    // pair matrix = P^2
    float ma = fmaf(pa, pa, pb * pc), mb = fmaf(pa, pb, pb * pd);
    float mc = fmaf(pc, pa, pd * pc), md = fmaf(pc, pb, pd * pd);

    // Kogge-Stone inclusive scan: self = self ∘ prev
#pragma unroll
    for (int d = 1; d < 32; d <<= 1) {
        float oa = __shfl_up_sync(FULL, ma, d);
        float ob = __shfl_up_sync(FULL, mb, d);
        float oc = __shfl_up_sync(FULL, mc, d);
        float od = __shfl_up_sync(FULL, md, d);
        float o1r = __shfl_up_sync(FULL, w1r, d);
        float o1i = __shfl_up_sync(FULL, w1i, d);
        float o2r = __shfl_up_sync(FULL, w2r, d);
        float o2i = __shfl_up_sync(FULL, w2i, d);
        if (lane >= d) {
            w1r = fmaf(ma, o1r, fmaf(mb, o2r, w1r));
            w1i = fmaf(ma, o1i, fmaf(mb, o2i, w1i));
            w2r = fmaf(mc, o1r, fmaf(md, o2r, w2r));
            w2i = fmaf(mc, o1i, fmaf(md, o2i, w2i));
            float na = fmaf(ma, oa, mb * oc), nb = fmaf(ma, ob, mb * od);
            float nc = fmaf(mc, oa, md * oc), nd = fmaf(mc, ob, md * od);
            ma = na; mb = nb; mc = nc; md = nd;
        }
    }

    // exclusive prefixes: init for chunk 2*lane is W_{lane-1} (0 at lane 0)
    float e1r = __shfl_up_sync(FULL, w1r, 1);
    float e1i = __shfl_up_sync(FULL, w1i, 1);
    float e2r = __shfl_up_sync(FULL, w2r, 1);
    float e2i = __shfl_up_sync(FULL, w2i, 1);
    if (lane == 0) { e1r = e1i = e2r = e2i = 0.0f; }

    float4* gi = reinterpret_cast<float4*>(g_init) + (size_t)(b * 256 + p) * 64;
    gi[2 * lane] = make_float4(e1r, e1i, e2r, e2i);
    // init for chunk 2*lane+1 = P*init + v0
    gi[2 * lane + 1] = make_float4(
        fmaf(pa, e1r, fmaf(pb, e2r, v0.x)),
        fmaf(pa, e1i, fmaf(pb, e2i, v0.y)),
        fmaf(pc, e1r, fmaf(pd, e2r, v0.z)),
        fmaf(pc, e1i, fmaf(pd, e2i, v0.w)));
}

// ---------------------------------------------------------------------------
// Scan phase 3: re-scan each chunk from corrected init, write ys (x2, interleaved)
// ---------------------------------------------------------------------------
__global__ void scan_final() {
    int b = blockIdx.x >> 6;
    int ch = blockIdx.x & 63;
    int p = threadIdx.x;
    float m11 = g_m11[p], m12 = g_m12[p], m21 = g_dts[p];
    float4 iv = reinterpret_cast<const float4*>(g_init)[(b * 256 + p) * 64 + ch];
    float x1r = iv.x, x1i = iv.y, x2r = iv.z, x2i = iv.w;
    const float2* f = reinterpret_cast<const float2*>(g_f)
                      + ((size_t)(b * Lc + ch * CLEN)) * 256 + p;
    float2* ys = reinterpret_cast<float2*>(g_ys)
                 + ((size_t)(b * Lc + ch * CLEN)) * 256 + p;
#pragma unroll 8
    for (int j = 0; j < CLEN; j++) {
        float2 fv = f[(size_t)j * 256];
        float n1r = fmaf(m11, x1r, fmaf(m12, x2r, fv.x));
        float n2r = fmaf(m21, x1r, x2r);
        float n1i = fmaf(m11, x1i, fmaf(m12, x2i, fv.y));
        float n2i = fmaf(m21, x1i, x2i);
        x1r = n1r; x2r = n2r; x1i = n1i; x2i = n2i;
        ys[(size_t)j * 256] = make_float2(x2r, x2i);
    }
}

// ---------------------------------------------------------------------------
extern "C" void kernel_launch(void* const* d_in, const int* in_sizes, int n_in,
                              void* d_out, int out_size) {
    const float* u  = (const float*)d_in[0];
    const float* Ad = (const float*)d_in[1];
    const float* Gd = (const float*)d_in[2];
    const float* dt = (const float*)d_in[3];
    const float* Bm = (const float*)d_in[4];
    const float* Cm = (const float*)d_in[5];
    const float* Dv = (const float*)d_in[6];
    float* out = (float*)d_out;

    float *fptr, *ysptr, *bop, *cop;
    cudaGetSymbolAddress((void**)&fptr,  g_f);
    cudaGetSymbolAddress((void**)&ysptr, g_ys);
    cudaGetSymbolAddress((void**)&bop,   g_Bop);
    cudaGetSymbolAddress((void**)&cop,   g_Cop);

    const int smem_bytes = (2 * 128 * 36 + 2 * 32 * 136) * 4; // 71680
    cudaFuncSetAttribute(gemm_tf32<512, 256, false>,
                         cudaFuncAttributeMaxDynamicSharedMemorySize, smem_bytes);
    cudaFuncSetAttribute(gemm_tf32<256, 512, true>,
                         cudaFuncAttributeMaxDynamicSharedMemorySize, smem_bytes);

    prep_kernel<<<256, 512>>>(Ad, Gd, dt, Bm, Cm);

    // GEMM1: f[bl][n(512)] = u[bl][h] @ Bop[h][n]
    gemm_tf32<512, 256, false><<<dim3(4, 256), 256, smem_bytes>>>(u, bop, fptr, nullptr, nullptr);

    scan_local  <<<Bc * NCHUNK, 256>>>();
    scan_combine<<<256, 256>>>();
    scan_final  <<<Bc * NCHUNK, 256>>>();

    // GEMM2: out[bl][h] = ys[bl][kk(512)] @ Cop[kk][h] + D[h]*u[bl][h]
    gemm_tf32<256, 512, true><<<dim3(2, 256), 256, smem_bytes>>>(ysptr, cop, out, u, Dv);
}